// round 1
// baseline (speedup 1.0000x reference)
#include <cuda_runtime.h>
#include <cstdint>
#include <cstdio>

// Problem constants
#define D        128
#define VD       64
#define TOPK     16
#define B_MAX    512
#define CHUNKS   74
#define QT       128
#define KT       128
#define QSTRIDE  130
#define EPS_F    1e-8f
#define INV_TEMP 4.0f
#define NEG_INF  (-1e30f)
#define CAND     (CHUNKS * 32)

// Scratch (static device arrays; no runtime allocation)
__device__ float g_qn[B_MAX * D];
__device__ float g_cval[B_MAX * CHUNKS * 32];
__device__ int   g_cidx[B_MAX * CHUNKS * 32];

// ---------------------------------------------------------------------------
// helpers
// ---------------------------------------------------------------------------
__device__ __forceinline__ unsigned long long dup2(float x) {
    unsigned long long r;
    asm("mov.b64 %0, {%1, %1};" : "=l"(r) : "f"(x));
    return r;
}
__device__ __forceinline__ void fma2(unsigned long long& a,
                                     unsigned long long x,
                                     unsigned long long y) {
    asm("fma.rn.f32x2 %0, %1, %2, %0;" : "+l"(a) : "l"(x), "l"(y));
}
__device__ __forceinline__ bool better(float v1, int i1, float v2, int i2) {
    return (v1 > v2) || (v1 == v2 && i1 < i2);
}

// ---------------------------------------------------------------------------
// Kernel 0: normalize queries, fold in 1/temperature
// ---------------------------------------------------------------------------
__global__ void normalize_kernel(const float* __restrict__ q) {
    int b = blockIdx.x;
    int t = threadIdx.x;                 // 128 threads
    float v = q[b * D + t];
    float ss = v * v;
    #pragma unroll
    for (int o = 16; o > 0; o >>= 1) ss += __shfl_xor_sync(0xffffffffu, ss, o);
    __shared__ float red[4];
    __shared__ float scale_s;
    if ((t & 31) == 0) red[t >> 5] = ss;
    __syncthreads();
    if (t == 0) {
        float n = sqrtf(red[0] + red[1] + red[2] + red[3]);
        scale_s = INV_TEMP / fmaxf(n, EPS_F);
    }
    __syncthreads();
    g_qn[b * D + t] = v * scale_s;
}

// ---------------------------------------------------------------------------
// Kernel 1: fused scores GEMM + per-chunk top-16
// grid: (CHUNKS, B/QT), block: 256
// dyn smem: qs[D][QSTRIDE] + ks[D][QSTRIDE] + sc[QT][KT]
// ---------------------------------------------------------------------------
extern "C" __global__ void __launch_bounds__(256, 1)
gemm_topk_kernel(const float* __restrict__ keys, int N, int S) {
    extern __shared__ float sm[];
    float* qs = sm;                       // transposed queries [d][q]
    float* ks = sm + D * QSTRIDE;         // transposed keys    [d][k]
    float* sc = ks + D * QSTRIDE;         // score tile, swizzled cols

    const int tid   = threadIdx.x;
    const int chunk = blockIdx.x;
    const int qbase = blockIdx.y * QT;
    const int start = chunk * S;
    const int cnt   = min(S, N - start);

    // --- load query tile, transposed (conflict-free STS: consecutive tid -> consecutive q) ---
    {
        int ql = tid & 127, dh = tid >> 7;
        const float4* src = (const float4*)&g_qn[(size_t)(qbase + ql) * D + dh * 64];
        #pragma unroll
        for (int j = 0; j < 16; ++j) {
            float4 v = src[j];
            int d0 = dh * 64 + j * 4;
            qs[(d0 + 0) * QSTRIDE + ql] = v.x;
            qs[(d0 + 1) * QSTRIDE + ql] = v.y;
            qs[(d0 + 2) * QSTRIDE + ql] = v.z;
            qs[(d0 + 3) * QSTRIDE + ql] = v.w;
        }
    }

    // per-thread top-16 (this thread scans half the keys of one query)
    float lv[TOPK];
    int   li[TOPK];
    #pragma unroll
    for (int i = 0; i < TOPK; ++i) { lv[i] = NEG_INF; li[i] = 0x7fffffff; }

    const int qg = tid & 15;     // query group (8 queries)
    const int kg = tid >> 4;     // key group   (8 keys = 4 packed pairs)
    const int sq = tid >> 1;     // scan: local query
    const int sh = tid & 1;      // scan: half (64 cols)

    const int ntiles = (cnt + KT - 1) / KT;
    for (int t = 0; t < ntiles; ++t) {
        __syncthreads();   // previous iteration's scan done; ks/sc reusable

        // --- load key tile, transposed; zero-pad beyond chunk ---
        {
            int kl = tid & 127, dh = tid >> 7;
            int klocal = t * KT + kl;
            if (klocal < cnt) {
                const float4* src =
                    (const float4*)(keys + (size_t)(start + klocal) * D + dh * 64);
                #pragma unroll
                for (int j = 0; j < 16; ++j) {
                    float4 v = src[j];
                    int d0 = dh * 64 + j * 4;
                    ks[(d0 + 0) * QSTRIDE + kl] = v.x;
                    ks[(d0 + 1) * QSTRIDE + kl] = v.y;
                    ks[(d0 + 2) * QSTRIDE + kl] = v.z;
                    ks[(d0 + 3) * QSTRIDE + kl] = v.w;
                }
            } else {
                #pragma unroll
                for (int j = 0; j < 16; ++j) {
                    int d0 = dh * 64 + j * 4;
                    ks[(d0 + 0) * QSTRIDE + kl] = 0.f;
                    ks[(d0 + 1) * QSTRIDE + kl] = 0.f;
                    ks[(d0 + 2) * QSTRIDE + kl] = 0.f;
                    ks[(d0 + 3) * QSTRIDE + kl] = 0.f;
                }
            }
        }
        __syncthreads();

        // --- compute 8q x 8k micro-tile with packed f32x2 FMA ---
        unsigned long long acc[8][4];
        #pragma unroll
        for (int i = 0; i < 8; ++i)
            #pragma unroll
            for (int j = 0; j < 4; ++j) acc[i][j] = 0ull;

        const float* qrow = qs + qg * 8;
        const float* krow = ks + kg * 8;
        #pragma unroll 4
        for (int d = 0; d < D; ++d) {
            const float* qd = qrow + d * QSTRIDE;
            const float* kd = krow + d * QSTRIDE;
            unsigned long long k0 = *(const unsigned long long*)(kd + 0);
            unsigned long long k1 = *(const unsigned long long*)(kd + 2);
            unsigned long long k2 = *(const unsigned long long*)(kd + 4);
            unsigned long long k3 = *(const unsigned long long*)(kd + 6);
            #pragma unroll
            for (int i = 0; i < 8; ++i) {
                unsigned long long qq = dup2(qd[i]);
                fma2(acc[i][0], qq, k0);
                fma2(acc[i][1], qq, k1);
                fma2(acc[i][2], qq, k2);
                fma2(acc[i][3], qq, k3);
            }
        }

        // --- stage scores to smem (column swizzle to stagger banks) ---
        #pragma unroll
        for (int i = 0; i < 8; ++i) {
            int q = qg * 8 + i;
            int e = qg * 2;                       // (q>>3)*2
            #pragma unroll
            for (int j = 0; j < 4; ++j) {
                int col = kg * 8 + j * 2;
                *(unsigned long long*)&sc[q * KT + (col ^ e)] = acc[i][j];
            }
        }
        __syncthreads();

        // --- scan: 2 threads per query, 64 scores each, threshold-gated insert ---
        {
            const int q = sq;
            const int e = (q >> 3) * 2;
            const int startj = ((q & 15) * 4 + sh * 2) & 63;  // bank stagger
            float thr = lv[TOPK - 1];
            for (int jj = 0; jj < 64; ++jj) {
                int j    = (startj + jj) & 63;
                int col  = sh * 64 + j;
                int kloc = t * KT + col;
                if (kloc >= cnt) continue;
                float v = sc[q * KT + (col ^ e)];
                int   gi = start + kloc;
                if (v > thr || (v == thr && gi < li[TOPK - 1])) {
                    lv[TOPK - 1] = v; li[TOPK - 1] = gi;
                    #pragma unroll
                    for (int m = TOPK - 1; m > 0; --m) {
                        if (better(lv[m], li[m], lv[m - 1], li[m - 1])) {
                            float tv = lv[m]; lv[m] = lv[m - 1]; lv[m - 1] = tv;
                            int   ti = li[m]; li[m] = li[m - 1]; li[m - 1] = ti;
                        }
                    }
                    thr = lv[TOPK - 1];
                }
            }
        }
    }

    // --- write the two 16-entry candidate lists for this (query, chunk) ---
    {
        int q = qbase + sq;
        long long base = ((long long)q * CHUNKS + chunk) * 32 + sh * TOPK;
        #pragma unroll
        for (int i = 0; i < TOPK; ++i) {
            g_cval[base + i] = lv[i];
            g_cidx[base + i] = li[i];
        }
    }
}

// ---------------------------------------------------------------------------
// Kernel 2: merge candidates -> exact top-16, softmax, gather, write outputs
// grid: B, block: 256
// ---------------------------------------------------------------------------
extern "C" __global__ void __launch_bounds__(256)
merge_kernel(const float* __restrict__ values, float* __restrict__ out,
             int Bn, int out_mode) {
    __shared__ float sv[CAND];
    __shared__ int   si[CAND];
    __shared__ float rv[256];
    __shared__ int   ri[256];
    __shared__ int   rp[256];
    __shared__ float topv[TOPK];
    __shared__ int   topi[TOPK];
    __shared__ float tw[TOPK];

    const int q = blockIdx.x, tid = threadIdx.x;
    const long long cb = (long long)q * CAND;
    for (int i = tid; i < CAND; i += 256) { sv[i] = g_cval[cb + i]; si[i] = g_cidx[cb + i]; }
    __syncthreads();

    for (int it = 0; it < TOPK; ++it) {
        float bv = NEG_INF; int bi = 0x7fffffff; int bp = -1;
        for (int i = tid; i < CAND; i += 256) {
            float v = sv[i]; int ii = si[i];
            if (better(v, ii, bv, bi)) { bv = v; bi = ii; bp = i; }
        }
        rv[tid] = bv; ri[tid] = bi; rp[tid] = bp;
        __syncthreads();
        for (int s = 128; s > 0; s >>= 1) {
            if (tid < s) {
                if (better(rv[tid + s], ri[tid + s], rv[tid], ri[tid])) {
                    rv[tid] = rv[tid + s]; ri[tid] = ri[tid + s]; rp[tid] = rp[tid + s];
                }
            }
            __syncthreads();
        }
        if (tid == 0) { topv[it] = rv[0]; topi[it] = ri[0]; sv[rp[0]] = NEG_INF; }
        __syncthreads();
    }

    if (tid == 0) {
        float m = topv[0];          // sorted descending -> max
        float s = 0.f;
        #pragma unroll
        for (int k = 0; k < TOPK; ++k) { float e = expf(topv[k] - m); tw[k] = e; s += e; }
        s += EPS_F;
        #pragma unroll
        for (int k = 0; k < TOPK; ++k) tw[k] = tw[k] / s;
    }
    __syncthreads();

    if (tid < VD) {
        float a = 0.f;
        #pragma unroll
        for (int k = 0; k < TOPK; ++k)
            a += tw[k] * values[(size_t)topi[k] * VD + tid];
        out[(size_t)q * VD + tid] = a;
    }
    if (out_mode) {
        if (tid >= 64 && tid < 64 + TOPK)
            out[(size_t)Bn * VD + (size_t)q * TOPK + (tid - 64)] = tw[tid - 64];
        if (tid >= 80 && tid < 80 + TOPK)
            out[(size_t)Bn * VD + (size_t)Bn * TOPK + (size_t)q * TOPK + (tid - 80)] =
                (float)topi[tid - 80];
    }
}

// ---------------------------------------------------------------------------
// launch
// ---------------------------------------------------------------------------
extern "C" void kernel_launch(void* const* d_in, const int* in_sizes, int n_in,
                              void* d_out, int out_size) {
    const float* queries = (const float*)d_in[0];
    const float* keys    = (const float*)d_in[1];
    const float* values  = (const float*)d_in[2];
    int Bn = in_sizes[0] / D;            // 512
    int N  = in_sizes[1] / D;            // 500000
    int S  = (N + CHUNKS - 1) / CHUNKS;  // chunk size

    normalize_kernel<<<Bn, D>>>(queries);

    size_t smem = (size_t)(2 * D * QSTRIDE + QT * KT) * sizeof(float);
    cudaFuncSetAttribute(gemm_topk_kernel,
                         cudaFuncAttributeMaxDynamicSharedMemorySize, (int)smem);
    dim3 grid(CHUNKS, Bn / QT);
    gemm_topk_kernel<<<grid, 256, smem>>>(keys, N, S);

    // output layout assumption: [retrieved(B*64) | topw(B*16) | topidx(B*16)] f32
    int out_mode = (out_size >= Bn * (VD + 2 * TOPK)) ? 1 : 0;
    merge_kernel<<<Bn, 256>>>(values, (float*)d_out, Bn, out_mode);
}

// round 3
// speedup vs baseline: 2.1317x; 2.1317x over previous
#include <cuda_runtime.h>
#include <cuda_fp16.h>
#include <cstdint>

// ---------------------------------------------------------------------------
// Problem constants
// ---------------------------------------------------------------------------
#define D        128
#define VD       64
#define TOPK     16
#define BQ       512
#define NCHUNK   74
#define KT       64                  // keys per tile
#define EPS_F    1e-8f
#define INV_TEMP 4.0f
#define NEG_INF  (-1e30f)
#define CPQ      (NCHUNK * TOPK)     // 1184 candidates per query
#define SEL      32                  // approx candidates rescored exactly

// smem layout (bytes)
#define A_OFF    0                   // 256 q x 128 k fp16, swizzled  = 65536
#define B_OFF    65536               // 2 bufs x (64 k x 128) fp16    = 32768
#define ST_OFF   98304               // fp32 key stage 64x128         = 32768
#define SC_OFF   131072              // scores 256 x 66 fp32          = 67584
#define SMEM_BYTES 198656

#define SC_STRIDE 66

// ---------------------------------------------------------------------------
// Scratch
// ---------------------------------------------------------------------------
__device__ float g_qn[BQ * D];
__device__ float g_cval[BQ * CPQ];
__device__ int   g_cidx[BQ * CPQ];

// ---------------------------------------------------------------------------
// helpers
// ---------------------------------------------------------------------------
__device__ __forceinline__ uint32_t smem_u32(const void* p) {
    uint32_t a;
    asm("{ .reg .u64 t; cvta.to.shared.u64 t, %1; cvt.u32.u64 %0, t; }"
        : "=r"(a) : "l"(p));
    return a;
}
__device__ __forceinline__ void cp_async16(uint32_t dst, const void* src) {
    asm volatile("cp.async.ca.shared.global [%0], [%1], 16;"
                 :: "r"(dst), "l"(src) : "memory");
}
#define CP_COMMIT() asm volatile("cp.async.commit_group;" ::: "memory")
#define CP_WAIT0()  asm volatile("cp.async.wait_group 0;"  ::: "memory")

__device__ __forceinline__ void ldm_x4(uint32_t addr, uint32_t& r0, uint32_t& r1,
                                       uint32_t& r2, uint32_t& r3) {
    asm volatile("ldmatrix.sync.aligned.m8n8.x4.shared.b16 {%0,%1,%2,%3}, [%4];"
                 : "=r"(r0), "=r"(r1), "=r"(r2), "=r"(r3) : "r"(addr));
}
__device__ __forceinline__ void mma16816(float& c0, float& c1, float& c2, float& c3,
                                         uint32_t a0, uint32_t a1, uint32_t a2, uint32_t a3,
                                         uint32_t b0, uint32_t b1) {
    asm volatile(
        "mma.sync.aligned.m16n8k16.row.col.f32.f16.f16.f32 "
        "{%0,%1,%2,%3}, {%4,%5,%6,%7}, {%8,%9}, {%0,%1,%2,%3};"
        : "+f"(c0), "+f"(c1), "+f"(c2), "+f"(c3)
        : "r"(a0), "r"(a1), "r"(a2), "r"(a3), "r"(b0), "r"(b1));
}
__device__ __forceinline__ bool better(float v1, int i1, float v2, int i2) {
    return (v1 > v2) || (v1 == v2 && i1 < i2);
}

// ---------------------------------------------------------------------------
// Kernel 0: normalize queries, fold in 1/temperature
// ---------------------------------------------------------------------------
__global__ void normalize_kernel(const float* __restrict__ q) {
    int b = blockIdx.x, t = threadIdx.x;  // 128 threads
    float v = q[b * D + t];
    float ss = v * v;
    #pragma unroll
    for (int o = 16; o > 0; o >>= 1) ss += __shfl_xor_sync(0xffffffffu, ss, o);
    __shared__ float red[4];
    __shared__ float scale_s;
    if ((t & 31) == 0) red[t >> 5] = ss;
    __syncthreads();
    if (t == 0) {
        float n = sqrtf(red[0] + red[1] + red[2] + red[3]);
        scale_s = INV_TEMP / fmaxf(n, EPS_F);
    }
    __syncthreads();
    g_qn[b * D + t] = v * scale_s;
}

// ---------------------------------------------------------------------------
// Kernel 1: fp16 mma.sync GEMM + per-chunk approx top-16
// grid (74, 2), block 256 (8 warps: 4 in M x 2 in N)
// ---------------------------------------------------------------------------
extern "C" __global__ void __launch_bounds__(256, 1)
score_topk_kernel(const float* __restrict__ keys, int N) {
    extern __shared__ __align__(1024) char smem[];
    const uint32_t sb = smem_u32(smem);
    float* sc = (float*)(smem + SC_OFF);

    const int tid  = threadIdx.x;
    const int lane = tid & 31;
    const int wid  = tid >> 5;
    const int wm   = wid & 3;       // M warp: rows wm*64 .. +63
    const int wn   = wid >> 2;      // N warp: cols wn*32 .. +31
    const int chunk = blockIdx.x;
    const int qhalf = blockIdx.y;

    const int ntTotal = (N + KT - 1) / KT;
    const int TPC     = (ntTotal + NCHUNK - 1) / NCHUNK;
    const int t0      = chunk * TPC;
    const int nt      = min(TPC, ntTotal - t0);

    // ---- build A tile: 256 queries x 128 dims fp16, swizzled ----
    #pragma unroll
    for (int i = 0; i < 16; ++i) {
        int idx = i * 256 + tid;        // 16B chunk id: 256 rows x 16 chunks
        int qr = idx >> 4, c16 = idx & 15;
        const float4* s = (const float4*)&g_qn[(size_t)(qhalf * 256 + qr) * D + c16 * 8];
        float4 f0 = s[0], f1 = s[1];
        __half2 h0 = __float22half2_rn(make_float2(f0.x, f0.y));
        __half2 h1 = __float22half2_rn(make_float2(f0.z, f0.w));
        __half2 h2 = __float22half2_rn(make_float2(f1.x, f1.y));
        __half2 h3 = __float22half2_rn(make_float2(f1.z, f1.w));
        uint4 pack = make_uint4(*(uint32_t*)&h0, *(uint32_t*)&h1,
                                *(uint32_t*)&h2, *(uint32_t*)&h3);
        int off = qr * 256 + ((c16 * 16) ^ ((qr & 7) << 4));
        *(uint4*)(smem + A_OFF + off) = pack;
    }

    // ---- prologue: load key tile 0 (fp32) via cp.async, convert to B buf0 ----
    if (nt > 0) {
        #pragma unroll
        for (int i = 0; i < 8; ++i) {
            int idx = i * 256 + tid;          // 16B chunks: 64 keys x 32 chunks
            int n = idx >> 5, c = idx & 31;
            int gk = t0 * KT + n;
            if (gk < N)
                cp_async16(sb + ST_OFF + n * 512 + c * 16,
                           keys + (size_t)gk * D + c * 4);
        }
        CP_COMMIT();
        CP_WAIT0();
        __syncthreads();
        #pragma unroll
        for (int i = 0; i < 4; ++i) {
            int idx = i * 256 + tid;          // 64 rows x 16 fp16-16B-chunks
            int n = idx >> 4, c16 = idx & 15;
            const float4* s = (const float4*)(smem + ST_OFF + n * 512 + c16 * 32);
            float4 f0 = s[0], f1 = s[1];
            __half2 h0 = __float22half2_rn(make_float2(f0.x, f0.y));
            __half2 h1 = __float22half2_rn(make_float2(f0.z, f0.w));
            __half2 h2 = __float22half2_rn(make_float2(f1.x, f1.y));
            __half2 h3 = __float22half2_rn(make_float2(f1.z, f1.w));
            uint4 pack = make_uint4(*(uint32_t*)&h0, *(uint32_t*)&h1,
                                    *(uint32_t*)&h2, *(uint32_t*)&h3);
            int off = n * 256 + ((c16 * 16) ^ ((n & 7) << 4));
            *(uint4*)(smem + B_OFF + off) = pack;
        }
    }

    // ---- per-lane invariant ldmatrix address components ----
    // A: 4 m-blocks; row = wm*64 + mb*16 + (lane&15); k-chunk += (lane>>4)*8
    uint32_t aBase[4];
    #pragma unroll
    for (int mb = 0; mb < 4; ++mb) {
        int row = wm * 64 + mb * 16 + (lane & 15);
        aBase[mb] = sb + A_OFF + row * 256 + (((row & 7) << 4) ^ ((lane >> 4) << 4));
    }
    // B: 2 x4-loads; row = wn*32 + g*16 + (lane&7) + ((lane>>4)<<3); k += ((lane>>3)&1)*8
    uint32_t bBase[2];
    #pragma unroll
    for (int g = 0; g < 2; ++g) {
        int row = wn * 32 + g * 16 + (lane & 7) + ((lane >> 4) << 3);
        bBase[g] = sb + B_OFF + row * 256 +
                   (((row & 7) << 4) ^ (((lane >> 3) & 1) << 4));
    }

    // per-thread top-16 for query tid
    float lv[TOPK]; int li[TOPK];
    #pragma unroll
    for (int i = 0; i < TOPK; ++i) { lv[i] = NEG_INF; li[i] = 0x7fffffff; }

    for (int t = 0; t < nt; ++t) {
        __syncthreads();   // B[t&1] conversion + (first iter) A build visible

        // prefetch key tile t+1 into fp32 stage
        if (t + 1 < nt) {
            #pragma unroll
            for (int i = 0; i < 8; ++i) {
                int idx = i * 256 + tid;
                int n = idx >> 5, c = idx & 31;
                int gk = (t0 + t + 1) * KT + n;
                if (gk < N)
                    cp_async16(sb + ST_OFF + n * 512 + c * 16,
                               keys + (size_t)gk * D + c * 4);
            }
            CP_COMMIT();
        }

        // ---- MMA: 256x64x128 tile; this warp: 64 rows x 32 cols ----
        float acc[4][4][4];
        #pragma unroll
        for (int mb = 0; mb < 4; ++mb)
            #pragma unroll
            for (int nb = 0; nb < 4; ++nb)
                #pragma unroll
                for (int r = 0; r < 4; ++r) acc[mb][nb][r] = 0.f;

        const uint32_t bufOff = (uint32_t)(t & 1) * 16384;
        #pragma unroll
        for (int ks = 0; ks < 8; ++ks) {
            uint32_t a[4][4], b[2][4];
            #pragma unroll
            for (int mb = 0; mb < 4; ++mb)
                ldm_x4(aBase[mb] ^ (ks * 32), a[mb][0], a[mb][1], a[mb][2], a[mb][3]);
            #pragma unroll
            for (int g = 0; g < 2; ++g)
                ldm_x4((bBase[g] + bufOff) ^ (ks * 32), b[g][0], b[g][1], b[g][2], b[g][3]);
            #pragma unroll
            for (int mb = 0; mb < 4; ++mb) {
                mma16816(acc[mb][0][0], acc[mb][0][1], acc[mb][0][2], acc[mb][0][3],
                         a[mb][0], a[mb][1], a[mb][2], a[mb][3], b[0][0], b[0][1]);
                mma16816(acc[mb][1][0], acc[mb][1][1], acc[mb][1][2], acc[mb][1][3],
                         a[mb][0], a[mb][1], a[mb][2], a[mb][3], b[0][2], b[0][3]);
                mma16816(acc[mb][2][0], acc[mb][2][1], acc[mb][2][2], acc[mb][2][3],
                         a[mb][0], a[mb][1], a[mb][2], a[mb][3], b[1][0], b[1][1]);
                mma16816(acc[mb][3][0], acc[mb][3][1], acc[mb][3][2], acc[mb][3][3],
                         a[mb][0], a[mb][1], a[mb][2], a[mb][3], b[1][2], b[1][3]);
            }
        }

        // ---- stage scores to smem ----
        {
            const int r4 = lane >> 2, c2 = (lane & 3) * 2;
            #pragma unroll
            for (int mb = 0; mb < 4; ++mb) {
                int q0 = wm * 64 + mb * 16 + r4;
                #pragma unroll
                for (int nb = 0; nb < 4; ++nb) {
                    int col = wn * 32 + nb * 8 + c2;
                    *(float2*)&sc[q0 * SC_STRIDE + col] =
                        make_float2(acc[mb][nb][0], acc[mb][nb][1]);
                    *(float2*)&sc[(q0 + 8) * SC_STRIDE + col] =
                        make_float2(acc[mb][nb][2], acc[mb][nb][3]);
                }
            }
        }
        CP_WAIT0();
        __syncthreads();   // scores visible; stage (t+1) ready

        // ---- scan: thread owns query tid, 64 cols ----
        {
            const int kb = (t0 + t) * KT;
            const float* row = sc + tid * SC_STRIDE;
            float thr = lv[TOPK - 1];
            #pragma unroll 1
            for (int j = 0; j < KT; ++j) {
                float v = row[j];
                int  gi = kb + j;
                if (gi < N && (v > thr || (v == thr && gi < li[TOPK - 1]))) {
                    lv[TOPK - 1] = v; li[TOPK - 1] = gi;
                    #pragma unroll
                    for (int m = TOPK - 1; m > 0; --m) {
                        if (better(lv[m], li[m], lv[m - 1], li[m - 1])) {
                            float tv = lv[m]; lv[m] = lv[m - 1]; lv[m - 1] = tv;
                            int   ti = li[m]; li[m] = li[m - 1]; li[m - 1] = ti;
                        }
                    }
                    thr = lv[TOPK - 1];
                }
            }
        }

        // ---- convert stage (tile t+1) into other B buf ----
        if (t + 1 < nt) {
            const uint32_t dstOff = B_OFF + (uint32_t)((t + 1) & 1) * 16384;
            #pragma unroll
            for (int i = 0; i < 4; ++i) {
                int idx = i * 256 + tid;
                int n = idx >> 4, c16 = idx & 15;
                const float4* s = (const float4*)(smem + ST_OFF + n * 512 + c16 * 32);
                float4 f0 = s[0], f1 = s[1];
                __half2 h0 = __float22half2_rn(make_float2(f0.x, f0.y));
                __half2 h1 = __float22half2_rn(make_float2(f0.z, f0.w));
                __half2 h2 = __float22half2_rn(make_float2(f1.x, f1.y));
                __half2 h3 = __float22half2_rn(make_float2(f1.z, f1.w));
                uint4 pack = make_uint4(*(uint32_t*)&h0, *(uint32_t*)&h1,
                                        *(uint32_t*)&h2, *(uint32_t*)&h3);
                int off = n * 256 + ((c16 * 16) ^ ((n & 7) << 4));
                *(uint4*)(smem + dstOff + off) = pack;
            }
        }
    }

    // ---- write candidate lists ----
    {
        int q = qhalf * 256 + tid;
        long long base = ((long long)q * NCHUNK + chunk) * TOPK;
        #pragma unroll
        for (int i = 0; i < TOPK; ++i) {
            g_cval[base + i] = lv[i];
            g_cidx[base + i] = li[i];
        }
    }
}

// ---------------------------------------------------------------------------
// Kernel 2: merge -> approx top-32 -> exact fp32 rescore -> top-16 ->
//           softmax -> weighted value gather
// ---------------------------------------------------------------------------
extern "C" __global__ void __launch_bounds__(256)
merge_kernel(const float* __restrict__ keys, const float* __restrict__ values,
             float* __restrict__ out, int Bn, int out_mode) {
    __shared__ float sv[CPQ];
    __shared__ int   si[CPQ];
    __shared__ float qsm[D];
    __shared__ float wv[8]; __shared__ int wiS[8]; __shared__ int wp[8];
    __shared__ int   selI[SEL];
    __shared__ float selV[SEL];
    __shared__ float topv[TOPK]; __shared__ int topi[TOPK]; __shared__ float tw[TOPK];

    const int q = blockIdx.x, tid = threadIdx.x;
    const int wid = tid >> 5, lane = tid & 31;
    const long long cb = (long long)q * CPQ;

    for (int i = tid; i < CPQ; i += 256) { sv[i] = g_cval[cb + i]; si[i] = g_cidx[cb + i]; }
    if (tid < D) qsm[tid] = g_qn[q * D + tid];
    __syncthreads();

    for (int it = 0; it < SEL; ++it) {
        float bv = NEG_INF; int bi = 0x7fffffff; int bp = -1;
        for (int i = tid; i < CPQ; i += 256) {
            float v = sv[i]; int ii = si[i];
            if (better(v, ii, bv, bi)) { bv = v; bi = ii; bp = i; }
        }
        #pragma unroll
        for (int o = 16; o > 0; o >>= 1) {
            float ov = __shfl_xor_sync(0xffffffffu, bv, o);
            int   oi = __shfl_xor_sync(0xffffffffu, bi, o);
            int   op = __shfl_xor_sync(0xffffffffu, bp, o);
            if (better(ov, oi, bv, bi)) { bv = ov; bi = oi; bp = op; }
        }
        if (lane == 0) { wv[wid] = bv; wiS[wid] = bi; wp[wid] = bp; }
        __syncthreads();
        if (tid == 0) {
            float cv = wv[0]; int ci = wiS[0], cp = wp[0];
            #pragma unroll
            for (int w = 1; w < 8; ++w)
                if (better(wv[w], wiS[w], cv, ci)) { cv = wv[w]; ci = wiS[w]; cp = wp[w]; }
            selI[it] = ci;
            sv[cp] = NEG_INF;
        }
        __syncthreads();
    }

    // exact fp32 rescore of the 32 selected candidates
    #pragma unroll
    for (int rep = 0; rep < 4; ++rep) {
        int s = rep * 8 + wid;
        int ki = selI[s];
        float4 kv = *(const float4*)&keys[(size_t)ki * D + lane * 4];
        float4 qv = ((const float4*)qsm)[lane];
        float p = kv.x * qv.x + kv.y * qv.y + kv.z * qv.z + kv.w * qv.w;
        #pragma unroll
        for (int o = 16; o > 0; o >>= 1) p += __shfl_xor_sync(0xffffffffu, p, o);
        if (lane == 0) selV[s] = p;
    }
    __syncthreads();

    if (tid == 0) {
        unsigned used = 0;
        for (int k = 0; k < TOPK; ++k) {
            float bv = NEG_INF; int bi = 0x7fffffff; int bs = 0;
            for (int s = 0; s < SEL; ++s) {
                if (used & (1u << s)) continue;
                if (better(selV[s], selI[s], bv, bi)) { bv = selV[s]; bi = selI[s]; bs = s; }
            }
            used |= 1u << bs;
            topv[k] = bv; topi[k] = bi;
        }
        float m = topv[0], sum = 0.f;
        #pragma unroll
        for (int k = 0; k < TOPK; ++k) { float e = expf(topv[k] - m); tw[k] = e; sum += e; }
        sum += EPS_F;
        #pragma unroll
        for (int k = 0; k < TOPK; ++k) tw[k] /= sum;
    }
    __syncthreads();

    if (tid < VD) {
        float a = 0.f;
        #pragma unroll
        for (int k = 0; k < TOPK; ++k)
            a += tw[k] * values[(size_t)topi[k] * VD + tid];
        out[(size_t)q * VD + tid] = a;
    }
    if (out_mode) {
        if (tid >= 64 && tid < 64 + TOPK)
            out[(size_t)Bn * VD + (size_t)q * TOPK + (tid - 64)] = tw[tid - 64];
        if (tid >= 80 && tid < 80 + TOPK)
            out[(size_t)Bn * VD + (size_t)Bn * TOPK + (size_t)q * TOPK + (tid - 80)] =
                (float)topi[tid - 80];
    }
}

// ---------------------------------------------------------------------------
// launch
// ---------------------------------------------------------------------------
extern "C" void kernel_launch(void* const* d_in, const int* in_sizes, int n_in,
                              void* d_out, int out_size) {
    const float* queries = (const float*)d_in[0];
    const float* keys    = (const float*)d_in[1];
    const float* values  = (const float*)d_in[2];
    int Bn = in_sizes[0] / D;   // 512
    int N  = in_sizes[1] / D;   // 500000

    normalize_kernel<<<Bn, D>>>(queries);

    cudaFuncSetAttribute(score_topk_kernel,
                         cudaFuncAttributeMaxDynamicSharedMemorySize, SMEM_BYTES);
    dim3 grid(NCHUNK, Bn / 256);
    score_topk_kernel<<<grid, 256, SMEM_BYTES>>>(keys, N);

    int out_mode = (out_size >= Bn * (VD + 2 * TOPK)) ? 1 : 0;
    merge_kernel<<<Bn, 256>>>(keys, values, (float*)d_out, Bn, out_mode);
}

// round 4
// speedup vs baseline: 3.4559x; 1.6212x over previous
#include <cuda_runtime.h>
#include <cuda_fp16.h>
#include <cstdint>

// ---------------------------------------------------------------------------
// Problem constants
// ---------------------------------------------------------------------------
#define D        128
#define VD       64
#define TOPK     16
#define TOPC     8                   // per (query,half,chunk) candidates
#define BQ       512
#define NCHUNK   74
#define KT       64                  // keys per tile
#define EPS_F    1e-8f
#define INV_TEMP 4.0f
#define NEG_INF  (-1e30f)
#define CPQ      (NCHUNK * 16)       // 1184 candidates per query
#define SEL      32
#define THREADS  512

// smem layout (bytes)
#define A_OFF    0                   // 256 q x 128 d fp16 swizzled   = 65536
#define B_OFF    65536               // 2 x (64 k x 128 d fp16)       = 32768
#define SC_OFF   98304               // 2 x (256 q x 64 k fp16)       = 65536
#define ST_OFF   163840              // 2 x 512 thread-slots x 72B    = 73728
#define SMEM_BYTES 237568
// NOTE: 237568 > 227KB?  65536+32768+65536+73728 = 237568 -> too big.
// Use single SC buffer is impossible (scan overlaps staging). Shrink stage
// stride to 68B: 2*512*68 = 69632 -> total 233472, still > 232448.
// Final choice: SC single-buffered per 128-query half? No. Instead stage
// stride 64B with +16B pad every 4 slots is complex; simplest: KT stays 64,
// stage stride 72 but only ONE stage buffer is needed if prefetch goes to
// registers?  -> We instead use stride 68 and shave B: B stays 32768.
// 65536+32768+65536+69632 = 233472. Over by 1024. Shave SC rotation pad? SC
// is exact. Shave A? exact. => drop stage to stride 66? 66 not /8.
// Use stage stride 68 and SC two buffers of 256x62?? No.
// Resolution: stage slots only need 64B data; put the two stage buffers
// interleaved with stride 72 but SHARED count 1008 slots? Cleanest: use
// stride 72 and reduce to 2x32KB by packing slot pad into bank-friendly
// XOR addressing instead of padding:
//   stage addr = base + ((slot*64) ^ ((slot & 1) << 4))
// slot*64: bank = slot*16 %32 -> {0,16}; XOR bit4 toggles 16B chunk; banks
// for LDS.128 phase (8 lanes, slots s..s+7):
//   chunk index = slot*4 + j  (64B = 4 chunks), xor flips chunk bit0 for odd
//   slots -> lanes still collide on banks {0..15} vs {16..31} pattern:
// slot even: banks (0..3)+16j ; slot odd: ... 2-way conflict only during the
// 4 convert LDS.128 per tile -> acceptable. Stage = 2 x 32768 exactly.
#undef ST_OFF
#undef SMEM_BYTES
#define ST_OFF   163840              // 2 x 32768
#define SMEM_TOTAL 229376            // 65536+32768+65536+65536 = 229376 <= 232448

// ---------------------------------------------------------------------------
// Scratch
// ---------------------------------------------------------------------------
__device__ float g_cval[BQ * CPQ];
__device__ int   g_cidx[BQ * CPQ];

// ---------------------------------------------------------------------------
// helpers
// ---------------------------------------------------------------------------
__device__ __forceinline__ uint32_t smem_u32(const void* p) {
    uint32_t a;
    asm("{ .reg .u64 t; cvta.to.shared.u64 t, %1; cvt.u32.u64 %0, t; }"
        : "=r"(a) : "l"(p));
    return a;
}
__device__ __forceinline__ void cp_async16(uint32_t dst, const void* src) {
    asm volatile("cp.async.ca.shared.global [%0], [%1], 16;"
                 :: "r"(dst), "l"(src) : "memory");
}
#define CP_COMMIT() asm volatile("cp.async.commit_group;" ::: "memory")
#define CP_WAIT(n)  asm volatile("cp.async.wait_group %0;" :: "n"(n) : "memory")

__device__ __forceinline__ void ldm_x4(uint32_t addr, uint32_t& r0, uint32_t& r1,
                                       uint32_t& r2, uint32_t& r3) {
    asm volatile("ldmatrix.sync.aligned.m8n8.x4.shared.b16 {%0,%1,%2,%3}, [%4];"
                 : "=r"(r0), "=r"(r1), "=r"(r2), "=r"(r3) : "r"(addr));
}
__device__ __forceinline__ void mma16816(float& c0, float& c1, float& c2, float& c3,
                                         uint32_t a0, uint32_t a1, uint32_t a2, uint32_t a3,
                                         uint32_t b0, uint32_t b1) {
    asm volatile(
        "mma.sync.aligned.m16n8k16.row.col.f32.f16.f16.f32 "
        "{%0,%1,%2,%3}, {%4,%5,%6,%7}, {%8,%9}, {%0,%1,%2,%3};"
        : "+f"(c0), "+f"(c1), "+f"(c2), "+f"(c3)
        : "r"(a0), "r"(a1), "r"(a2), "r"(a3), "r"(b0), "r"(b1));
}
__device__ __forceinline__ bool better(float v1, int i1, float v2, int i2) {
    return (v1 > v2) || (v1 == v2 && i1 < i2);
}

// score-stage addressing: row q (0..255) x 64 fp16 cols, 128B rows,
// 16B chunks rotated by (q&7) to decouple banks from the row stride.
__device__ __forceinline__ uint32_t sc_addr(uint32_t base, int buf, int q, int col) {
    int chunk = col >> 3;
    int rot = (chunk + (q & 7)) & 7;
    return base + SC_OFF + buf * 32768 + q * 128 + rot * 16 + (col & 7) * 2;
}
// stage slot addressing (64B per thread slot, xor to break bank aliasing)
__device__ __forceinline__ uint32_t st_addr(uint32_t base, int buf, int slot, int j16) {
    uint32_t off = (uint32_t)slot * 64 + (uint32_t)j16 * 16;
    off ^= ((slot & 1) << 4);
    return base + ST_OFF + buf * 32768 + off;
}

// ---------------------------------------------------------------------------
// Kernel 1: fused normalize + fp16 mma GEMM + per-chunk approx top-8x2
// grid (74, 2), block 512 (16 warps: 8 in M x 2 in N)
// ---------------------------------------------------------------------------
extern "C" __global__ void __launch_bounds__(THREADS, 1)
score_topk_kernel(const float* __restrict__ queries,
                  const float* __restrict__ keys, int N) {
    extern __shared__ __align__(1024) char smem[];
    const uint32_t sb = smem_u32(smem);

    const int tid  = threadIdx.x;
    const int lane = tid & 31;
    const int wid  = tid >> 5;
    const int wm   = wid >> 1;      // 0..7 : rows wm*32 .. +31
    const int wn   = wid & 1;       // 0..1 : cols wn*32 .. +31
    const int chunk = blockIdx.x;
    const int qhalf = blockIdx.y;

    const int ntTotal = (N + KT - 1) / KT;
    const int TPC     = (ntTotal + NCHUNK - 1) / NCHUNK;
    const int t0      = chunk * TPC;
    const int nt      = min(TPC, ntTotal - t0);

    // ---- prologue A: normalize queries + build fp16 A tile ----
    {
        int row = tid >> 1, half = tid & 1;
        float4 v[16];
        const float4* src =
            (const float4*)&queries[(size_t)(qhalf * 256 + row) * D + half * 64];
        float ss = 0.f;
        #pragma unroll
        for (int j = 0; j < 16; ++j) {
            v[j] = src[j];
            ss += v[j].x * v[j].x + v[j].y * v[j].y + v[j].z * v[j].z + v[j].w * v[j].w;
        }
        ss += __shfl_xor_sync(0xffffffffu, ss, 1);
        float scale = INV_TEMP / fmaxf(sqrtf(ss), EPS_F);
        #pragma unroll
        for (int j = 0; j < 8; ++j) {
            float4 f0 = v[j * 2], f1 = v[j * 2 + 1];
            __half2 h0 = __float22half2_rn(make_float2(f0.x * scale, f0.y * scale));
            __half2 h1 = __float22half2_rn(make_float2(f0.z * scale, f0.w * scale));
            __half2 h2 = __float22half2_rn(make_float2(f1.x * scale, f1.y * scale));
            __half2 h3 = __float22half2_rn(make_float2(f1.z * scale, f1.w * scale));
            uint4 pack = make_uint4(*(uint32_t*)&h0, *(uint32_t*)&h1,
                                    *(uint32_t*)&h2, *(uint32_t*)&h3);
            int c16 = half * 8 + j;
            int off = row * 256 + ((c16 * 16) ^ ((row & 7) << 4));
            *(uint4*)(smem + A_OFF + off) = pack;
        }
    }

    // key-loader identity: this thread owns key n = tid>>3, dims (tid&7)*16..+15
    const int kn = tid >> 3;
    const int kd = (tid & 7) * 16;

    // issue tile0 -> stage0, tile1 -> stage1
    #pragma unroll
    for (int b = 0; b < 2; ++b) {
        if (b < nt) {
            int gk = (t0 + b) * KT + kn;
            if (gk < N) {
                const float* src = keys + (size_t)gk * D + kd;
                #pragma unroll
                for (int j = 0; j < 4; ++j)
                    cp_async16(st_addr(sb, b, tid, j), src + j * 4);
            } else {
                uint4 z = make_uint4(0, 0, 0, 0);
                #pragma unroll
                for (int j = 0; j < 4; ++j)
                    *(uint4*)(smem + (st_addr(sb, b, tid, j) - sb)) = z;
            }
        }
        CP_COMMIT();
    }

    // convert stage0 -> B0 (own cells only; wait only our older group)
    CP_WAIT(1);
    {
        float4 f[4];
        #pragma unroll
        for (int j = 0; j < 4; ++j)
            f[j] = *(const float4*)(smem + (st_addr(sb, 0, tid, j) - sb));
        #pragma unroll
        for (int p = 0; p < 2; ++p) {
            float4 a = f[p * 2], b = f[p * 2 + 1];
            __half2 h0 = __float22half2_rn(make_float2(a.x, a.y));
            __half2 h1 = __float22half2_rn(make_float2(a.z, a.w));
            __half2 h2 = __float22half2_rn(make_float2(b.x, b.y));
            __half2 h3 = __float22half2_rn(make_float2(b.z, b.w));
            uint4 pack = make_uint4(*(uint32_t*)&h0, *(uint32_t*)&h1,
                                    *(uint32_t*)&h2, *(uint32_t*)&h3);
            int c16 = (kd >> 3) + p;
            int off = kn * 256 + ((c16 * 16) ^ ((kn & 7) << 4));
            *(uint4*)(smem + B_OFF + off) = pack;
        }
    }
    __syncthreads();

    // ---- ldmatrix invariant addresses ----
    uint32_t aBase[2];
    #pragma unroll
    for (int mb = 0; mb < 2; ++mb) {
        int row = wm * 32 + mb * 16 + (lane & 15);
        aBase[mb] = sb + A_OFF + row * 256 + (((row & 7) << 4) ^ ((lane >> 4) << 4));
    }
    uint32_t bBase[2];
    #pragma unroll
    for (int g = 0; g < 2; ++g) {
        int row = wn * 32 + g * 16 + (lane & 7) + ((lane >> 4) << 3);
        bBase[g] = sb + B_OFF + row * 256 +
                   (((row & 7) << 4) ^ (((lane >> 3) & 1) << 4));
    }

    // per-thread top-8 for (query tid>>1, half tid&1)
    float lv[TOPC]; int li[TOPC];
    #pragma unroll
    for (int i = 0; i < TOPC; ++i) { lv[i] = NEG_INF; li[i] = 0x7fffffff; }
    const int sq = tid >> 1;        // scan query
    const int shh = tid & 1;        // scan half (cols shh*32..+31)

    const int r4 = lane >> 2, c2 = (lane & 3) * 2;

    for (int t = 0; t < nt; ++t) {
        // ---- MMA on B[t&1]: warp computes 32 rows x 32 cols ----
        float acc[2][4][4];
        #pragma unroll
        for (int mb = 0; mb < 2; ++mb)
            #pragma unroll
            for (int nb = 0; nb < 4; ++nb)
                #pragma unroll
                for (int r = 0; r < 4; ++r) acc[mb][nb][r] = 0.f;

        const uint32_t bufOff = (uint32_t)(t & 1) * 16384;
        #pragma unroll
        for (int ks = 0; ks < 8; ++ks) {
            uint32_t a[2][4], b[2][4];
            #pragma unroll
            for (int mb = 0; mb < 2; ++mb)
                ldm_x4(aBase[mb] ^ (ks * 32), a[mb][0], a[mb][1], a[mb][2], a[mb][3]);
            #pragma unroll
            for (int g = 0; g < 2; ++g)
                ldm_x4((bBase[g] + bufOff) ^ (ks * 32), b[g][0], b[g][1], b[g][2], b[g][3]);
            #pragma unroll
            for (int mb = 0; mb < 2; ++mb) {
                mma16816(acc[mb][0][0], acc[mb][0][1], acc[mb][0][2], acc[mb][0][3],
                         a[mb][0], a[mb][1], a[mb][2], a[mb][3], b[0][0], b[0][1]);
                mma16816(acc[mb][1][0], acc[mb][1][1], acc[mb][1][2], acc[mb][1][3],
                         a[mb][0], a[mb][1], a[mb][2], a[mb][3], b[0][2], b[0][3]);
                mma16816(acc[mb][2][0], acc[mb][2][1], acc[mb][2][2], acc[mb][2][3],
                         a[mb][0], a[mb][1], a[mb][2], a[mb][3], b[1][0], b[1][1]);
                mma16816(acc[mb][3][0], acc[mb][3][1], acc[mb][3][2], acc[mb][3][3],
                         a[mb][0], a[mb][1], a[mb][2], a[mb][3], b[1][2], b[1][3]);
            }
        }

        // ---- stage fp16 scores -> SC[t&1] (conflict-free STS.32) ----
        #pragma unroll
        for (int mb = 0; mb < 2; ++mb) {
            int q0 = wm * 32 + mb * 16 + r4;
            #pragma unroll
            for (int nb = 0; nb < 4; ++nb) {
                int col = wn * 32 + nb * 8 + c2;
                __half2 lo = __float22half2_rn(make_float2(acc[mb][nb][0], acc[mb][nb][1]));
                __half2 hi = __float22half2_rn(make_float2(acc[mb][nb][2], acc[mb][nb][3]));
                *(uint32_t*)(smem + (sc_addr(sb, t & 1, q0, col) - sb)) = *(uint32_t*)&lo;
                *(uint32_t*)(smem + (sc_addr(sb, t & 1, q0 + 8, col) - sb)) = *(uint32_t*)&hi;
            }
        }

        // ---- prefetch/convert for tile t+1 (self-owned cells) ----
        if (t + 1 < nt) {
            CP_WAIT(0);   // group (t+1) done for this thread
            const int cbuf = (t + 1) & 1;
            float4 f[4];
            #pragma unroll
            for (int j = 0; j < 4; ++j)
                f[j] = *(const float4*)(smem + (st_addr(sb, cbuf, tid, j) - sb));
            #pragma unroll
            for (int p = 0; p < 2; ++p) {
                float4 fa = f[p * 2], fb = f[p * 2 + 1];
                __half2 h0 = __float22half2_rn(make_float2(fa.x, fa.y));
                __half2 h1 = __float22half2_rn(make_float2(fa.z, fa.w));
                __half2 h2 = __float22half2_rn(make_float2(fb.x, fb.y));
                __half2 h3 = __float22half2_rn(make_float2(fb.z, fb.w));
                uint4 pack = make_uint4(*(uint32_t*)&h0, *(uint32_t*)&h1,
                                        *(uint32_t*)&h2, *(uint32_t*)&h3);
                int c16 = (kd >> 3) + p;
                int off = kn * 256 + ((c16 * 16) ^ ((kn & 7) << 4));
                *(uint4*)(smem + B_OFF + cbuf * 16384 + off) = pack;
            }
            if (t + 2 < nt) {
                int gk = (t0 + t + 2) * KT + kn;
                int sbuf = t & 1;
                if (gk < N) {
                    const float* src = keys + (size_t)gk * D + kd;
                    #pragma unroll
                    for (int j = 0; j < 4; ++j)
                        cp_async16(st_addr(sb, sbuf, tid, j), src + j * 4);
                } else {
                    uint4 z = make_uint4(0, 0, 0, 0);
                    #pragma unroll
                    for (int j = 0; j < 4; ++j)
                        *(uint4*)(smem + (st_addr(sb, sbuf, tid, j) - sb)) = z;
                }
            }
            CP_COMMIT();
        }

        // ---- scan tile t-1 from SC[(t-1)&1] ----
        if (t > 0) {
            const int kb = (t0 + t - 1) * KT;
            float thr = lv[TOPC - 1];
            #pragma unroll
            for (int j = 0; j < 4; ++j) {
                uint4 w = *(const uint4*)(smem +
                        (sc_addr(sb, (t - 1) & 1, sq, shh * 32 + j * 8) - sb));
                const uint32_t* ww = (const uint32_t*)&w;
                #pragma unroll
                for (int h = 0; h < 4; ++h) {
                    float2 fv = __half22float2(*(const __half2*)&ww[h]);
                    #pragma unroll
                    for (int e = 0; e < 2; ++e) {
                        float v = e ? fv.y : fv.x;
                        int gi = kb + shh * 32 + j * 8 + h * 2 + e;
                        if (gi < N && (v > thr || (v == thr && gi < li[TOPC - 1]))) {
                            lv[TOPC - 1] = v; li[TOPC - 1] = gi;
                            #pragma unroll
                            for (int m = TOPC - 1; m > 0; --m) {
                                if (better(lv[m], li[m], lv[m - 1], li[m - 1])) {
                                    float tv = lv[m]; lv[m] = lv[m - 1]; lv[m - 1] = tv;
                                    int   ti = li[m]; li[m] = li[m - 1]; li[m - 1] = ti;
                                }
                            }
                            thr = lv[TOPC - 1];
                        }
                    }
                }
            }
        }

        __syncthreads();
    }

    // ---- tail scan: tile nt-1 ----
    {
        const int kb = (t0 + nt - 1) * KT;
        float thr = lv[TOPC - 1];
        #pragma unroll
        for (int j = 0; j < 4; ++j) {
            uint4 w = *(const uint4*)(smem +
                    (sc_addr(sb, (nt - 1) & 1, sq, shh * 32 + j * 8) - sb));
            const uint32_t* ww = (const uint32_t*)&w;
            #pragma unroll
            for (int h = 0; h < 4; ++h) {
                float2 fv = __half22float2(*(const __half2*)&ww[h]);
                #pragma unroll
                for (int e = 0; e < 2; ++e) {
                    float v = e ? fv.y : fv.x;
                    int gi = kb + shh * 32 + j * 8 + h * 2 + e;
                    if (gi < N && (v > thr || (v == thr && gi < li[TOPC - 1]))) {
                        lv[TOPC - 1] = v; li[TOPC - 1] = gi;
                        #pragma unroll
                        for (int m = TOPC - 1; m > 0; --m) {
                            if (better(lv[m], li[m], lv[m - 1], li[m - 1])) {
                                float tv = lv[m]; lv[m] = lv[m - 1]; lv[m - 1] = tv;
                                int   ti = li[m]; li[m] = li[m - 1]; li[m - 1] = ti;
                            }
                        }
                        thr = lv[TOPC - 1];
                    }
                }
            }
        }
    }

    // ---- write candidates: 8 per (query, half, chunk) ----
    {
        int q = qhalf * 256 + sq;
        long long base = ((long long)q * NCHUNK + chunk) * 16 + shh * TOPC;
        #pragma unroll
        for (int i = 0; i < TOPC; ++i) {
            g_cval[base + i] = lv[i];
            g_cidx[base + i] = li[i];
        }
    }
}

// ---------------------------------------------------------------------------
// Kernel 2: merge -> approx top-32 -> exact fp32 rescore -> top-16 ->
//           softmax -> weighted value gather
// ---------------------------------------------------------------------------
extern "C" __global__ void __launch_bounds__(256)
merge_kernel(const float* __restrict__ queries, const float* __restrict__ keys,
             const float* __restrict__ values, float* __restrict__ out,
             int Bn, int out_mode) {
    __shared__ float sv[CPQ];
    __shared__ int   si[CPQ];
    __shared__ float qsm[D];
    __shared__ float wv[8]; __shared__ int wiS[8]; __shared__ int wp[8];
    __shared__ int   selI[SEL];
    __shared__ float selV[SEL];
    __shared__ float topv[TOPK]; __shared__ int topi[TOPK]; __shared__ float tw[TOPK];

    const int q = blockIdx.x, tid = threadIdx.x;
    const int wid = tid >> 5, lane = tid & 31;
    const long long cb = (long long)q * CPQ;

    for (int i = tid; i < CPQ; i += 256) { sv[i] = g_cval[cb + i]; si[i] = g_cidx[cb + i]; }
    // normalized query (warp 0)
    if (wid == 0) {
        float4 v = *(const float4*)&queries[(size_t)q * D + lane * 4];
        float ss = v.x * v.x + v.y * v.y + v.z * v.z + v.w * v.w;
        #pragma unroll
        for (int o = 16; o > 0; o >>= 1) ss += __shfl_xor_sync(0xffffffffu, ss, o);
        float scale = INV_TEMP / fmaxf(sqrtf(ss), EPS_F);
        *(float4*)&qsm[lane * 4] = make_float4(v.x * scale, v.y * scale,
                                               v.z * scale, v.w * scale);
    }
    __syncthreads();

    for (int it = 0; it < SEL; ++it) {
        float bv = NEG_INF; int bi = 0x7fffffff; int bp = -1;
        for (int i = tid; i < CPQ; i += 256) {
            float v = sv[i]; int ii = si[i];
            if (better(v, ii, bv, bi)) { bv = v; bi = ii; bp = i; }
        }
        #pragma unroll
        for (int o = 16; o > 0; o >>= 1) {
            float ov = __shfl_xor_sync(0xffffffffu, bv, o);
            int   oi = __shfl_xor_sync(0xffffffffu, bi, o);
            int   op = __shfl_xor_sync(0xffffffffu, bp, o);
            if (better(ov, oi, bv, bi)) { bv = ov; bi = oi; bp = op; }
        }
        if (lane == 0) { wv[wid] = bv; wiS[wid] = bi; wp[wid] = bp; }
        __syncthreads();
        if (tid == 0) {
            float cv = wv[0]; int ci = wiS[0], cp = wp[0];
            #pragma unroll
            for (int w = 1; w < 8; ++w)
                if (better(wv[w], wiS[w], cv, ci)) { cv = wv[w]; ci = wiS[w]; cp = wp[w]; }
            selI[it] = ci;
            sv[cp] = NEG_INF;
        }
        __syncthreads();
    }

    // exact fp32 rescore of SEL candidates
    #pragma unroll
    for (int rep = 0; rep < 4; ++rep) {
        int s = rep * 8 + wid;
        int ki = selI[s];
        float4 kv = *(const float4*)&keys[(size_t)ki * D + lane * 4];
        float4 qv = ((const float4*)qsm)[lane];
        float p = kv.x * qv.x + kv.y * qv.y + kv.z * qv.z + kv.w * qv.w;
        #pragma unroll
        for (int o = 16; o > 0; o >>= 1) p += __shfl_xor_sync(0xffffffffu, p, o);
        if (lane == 0) selV[s] = p;
    }
    __syncthreads();

    if (tid == 0) {
        unsigned used = 0;
        for (int k = 0; k < TOPK; ++k) {
            float bv = NEG_INF; int bi = 0x7fffffff; int bs = 0;
            for (int s = 0; s < SEL; ++s) {
                if (used & (1u << s)) continue;
                if (better(selV[s], selI[s], bv, bi)) { bv = selV[s]; bi = selI[s]; bs = s; }
            }
            used |= 1u << bs;
            topv[k] = bv; topi[k] = bi;
        }
        float m = topv[0], sum = 0.f;
        #pragma unroll
        for (int k = 0; k < TOPK; ++k) { float e = expf(topv[k] - m); tw[k] = e; sum += e; }
        sum += EPS_F;
        #pragma unroll
        for (int k = 0; k < TOPK; ++k) tw[k] /= sum;
    }
    __syncthreads();

    if (tid < VD) {
        float a = 0.f;
        #pragma unroll
        for (int k = 0; k < TOPK; ++k)
            a += tw[k] * values[(size_t)topi[k] * VD + tid];
        out[(size_t)q * VD + tid] = a;
    }
    if (out_mode) {
        if (tid >= 64 && tid < 64 + TOPK)
            out[(size_t)Bn * VD + (size_t)q * TOPK + (tid - 64)] = tw[tid - 64];
        if (tid >= 80 && tid < 80 + TOPK)
            out[(size_t)Bn * VD + (size_t)Bn * TOPK + (size_t)q * TOPK + (tid - 80)] =
                (float)topi[tid - 80];
    }
}

// ---------------------------------------------------------------------------
// launch
// ---------------------------------------------------------------------------
extern "C" void kernel_launch(void* const* d_in, const int* in_sizes, int n_in,
                              void* d_out, int out_size) {
    const float* queries = (const float*)d_in[0];
    const float* keys    = (const float*)d_in[1];
    const float* values  = (const float*)d_in[2];
    int Bn = in_sizes[0] / D;   // 512
    int N  = in_sizes[1] / D;   // 500000

    cudaFuncSetAttribute(score_topk_kernel,
                         cudaFuncAttributeMaxDynamicSharedMemorySize, SMEM_TOTAL);
    dim3 grid(NCHUNK, Bn / 256);
    score_topk_kernel<<<grid, THREADS, SMEM_TOTAL>>>(queries, keys, N);

    int out_mode = (out_size >= Bn * (VD + 2 * TOPK)) ? 1 : 0;
    merge_kernel<<<Bn, 256>>>(queries, keys, values, (float*)d_out, Bn, out_mode);
}